// round 10
// baseline (speedup 1.0000x reference)
#include <cuda_runtime.h>
#include <cuda_fp16.h>

#define NN 50000
#define NE 600000
#define DD 128
#define CSR_B 1024
#define CSR_G 49                        // ceil(NN/1024); all co-resident (<=148 SMs)
#define CSR_NT (CSR_B * CSR_G)          // 50176

// ---------------- scratch (static device globals; no allocation) ----------------
__device__ __half g_xwh[NN * DD];               // x @ W in fp16, 12.8 MB (L2-resident)
__device__ int    g_degi[NN];                   // zero at load; csr phase B re-zeroes
__device__ int    g_start[NN];
__device__ int    g_cur[NN];
__device__ unsigned int g_adj[NE];              // src per edge (CSR by dst)
__device__ float  g_dinv[NN];
__device__ int    g_bsum[CSR_G];
__device__ float  g_sum[DD];                    // zeroed in csr phase A each run
__device__ float  g_sumsq[DD];
__device__ unsigned int g_count;                // barrier count (self-resets to 0)
__device__ volatile unsigned int g_gen;         // barrier generation (monotonic)

// ---- local int64/int32 detection: values < 50000 => int64 odd words all zero ----
__device__ __forceinline__ int detect_is64(const unsigned int* __restrict__ e) {
    int is64 = 1;
    #pragma unroll
    for (int i = 0; i < 16; i++)
        if (e[2 * i + 1] != 0u) { is64 = 0; break; }
    return is64;
}

// -------- generation-based grid barrier for the 49 co-resident csr blocks --------
__device__ __forceinline__ void csr_grid_sync() {
    __threadfence();
    __syncthreads();
    if (threadIdx.x == 0) {
        unsigned int gen = g_gen;
        if (atomicAdd(&g_count, 1) == CSR_G - 1) {
            atomicExch(&g_count, 0);
            __threadfence();
            g_gen = gen + 1;
        } else {
            while (g_gen == gen) __nanosleep(32);
            __threadfence();
        }
    }
    __syncthreads();
}

// ---------------- degree over dst ----------------
__global__ void deg_kernel(const unsigned int* __restrict__ e) {
    __shared__ int s64;
    if (threadIdx.x == 0) s64 = detect_is64(e);
    __syncthreads();
    int t = blockIdx.x * blockDim.x + threadIdx.x;
    if (t >= NE) return;
    int d;
    if (s64) d = (int)((const long long*)e)[NE + t];
    else     d = ((const int*)e)[NE + t];
    atomicAdd(&g_degi[d], 1);
}

// ------- csr: dinv + scan + start/cur + grid sync + adjacency fill ----------------
__global__ void __launch_bounds__(CSR_B) csr_kernel(const unsigned int* __restrict__ e) {
    __shared__ int wsums[32];
    __shared__ int bpart[2];
    __shared__ int s64;
    const int tid = threadIdx.x, lane = tid & 31, wid = tid >> 5;
    const int bid = blockIdx.x;

    if (tid == 0) s64 = detect_is64(e);
    if (bid == 0 && tid < DD) { g_sum[tid] = 0.0f; g_sumsq[tid] = 0.0f; }

    // ---- phase A: dinv + block-local inclusive scan ----
    const int i = bid * CSR_B + tid;
    int d = (i < NN) ? g_degi[i] : 0;
    if (i < NN) g_dinv[i] = rsqrtf((float)d + 1.0f);   // +1 = self loop

    int v = d;
    #pragma unroll
    for (int o = 1; o < 32; o <<= 1) {
        int t = __shfl_up_sync(0xffffffffu, v, o);
        if (lane >= o) v += t;
    }
    if (lane == 31) wsums[wid] = v;
    __syncthreads();
    if (wid == 0) {
        int wv = wsums[lane];
        #pragma unroll
        for (int o = 1; o < 32; o <<= 1) {
            int t = __shfl_up_sync(0xffffffffu, wv, o);
            if (lane >= o) wv += t;
        }
        wsums[lane] = wv;
    }
    __syncthreads();
    if (tid == 0) g_bsum[bid] = wsums[31];

    csr_grid_sync();                     // all block totals published

    if (tid < 64) {
        int t = (tid < bid) ? g_bsum[tid] : 0;
        #pragma unroll
        for (int o = 16; o > 0; o >>= 1) t += __shfl_down_sync(0xffffffffu, t, o);
        if ((tid & 31) == 0) bpart[tid >> 5] = t;
    }
    __syncthreads();
    if (i < NN) {
        int excl = bpart[0] + bpart[1] + (wid > 0 ? wsums[wid - 1] : 0) + (v - d);
        g_start[i] = excl;
        g_cur[i]   = excl;
    }

    csr_grid_sync();                     // all start/cur written

    // ---- phase B: adjacency fill (grid-stride) + re-zero degi for next replay ----
    const int is64 = s64;
    const int gid  = bid * CSR_B + tid;
    for (int t = gid; t < NN; t += CSR_NT) g_degi[t] = 0;
    for (int t = gid; t < NE; t += CSR_NT) {
        int s, dd;
        if (is64) {
            s  = (int)((const long long*)e)[t];
            dd = (int)((const long long*)e)[NE + t];
        } else {
            s  = ((const int*)e)[t];
            dd = ((const int*)e)[NE + t];
        }
        int p = atomicAdd(&g_cur[dd], 1);
        g_adj[p] = (unsigned int)s;
    }
}

// --------- GEMM: g_xwh = fp16(x @ W), packed fma.rn.f32x2, fp16 epilogue ---------
__global__ void __launch_bounds__(128) gemm_kernel(const float* __restrict__ x,
                                                   const float* __restrict__ W) {
    __shared__ unsigned long long xs[32][DD];   // 32 KB
    const int tid = threadIdx.x;
    const int r0  = blockIdx.x * 32;

    for (int idx = tid; idx < 32 * DD; idx += 128) {
        int row = idx >> 7, k = idx & 127;
        float v = (r0 + row < NN) ? x[(size_t)(r0 + row) * DD + k] : 0.0f;
        unsigned int u = __float_as_uint(v);
        xs[row][k] = ((unsigned long long)u << 32) | u;
    }
    __syncthreads();

    const int cg = tid & 31;
    const int rg = tid >> 5;
    unsigned long long a[8][2];
    #pragma unroll
    for (int r = 0; r < 8; r++) { a[r][0] = 0ull; a[r][1] = 0ull; }

    const float4* __restrict__ W4 = (const float4*)W;
    #pragma unroll 4
    for (int k = 0; k < DD; k++) {
        float4 w = W4[k * 32 + cg];
        unsigned long long wxy, wzw;
        asm("mov.b64 %0, {%1,%2};" : "=l"(wxy) : "f"(w.x), "f"(w.y));
        asm("mov.b64 %0, {%1,%2};" : "=l"(wzw) : "f"(w.z), "f"(w.w));
        #pragma unroll
        for (int r = 0; r < 8; r++) {
            unsigned long long xd = xs[rg * 8 + r][k];
            asm("fma.rn.f32x2 %0, %1, %2, %0;" : "+l"(a[r][0]) : "l"(xd), "l"(wxy));
            asm("fma.rn.f32x2 %0, %1, %2, %0;" : "+l"(a[r][1]) : "l"(xd), "l"(wzw));
        }
    }

    uint2* __restrict__ outh = (uint2*)g_xwh;   // row = 32 uint2 (4 halves each)
    #pragma unroll
    for (int r = 0; r < 8; r++) {
        int row = r0 + rg * 8 + r;
        if (row < NN) {
            float4 o;
            asm("mov.b64 {%0,%1}, %2;" : "=f"(o.x), "=f"(o.y) : "l"(a[r][0]));
            asm("mov.b64 {%0,%1}, %2;" : "=f"(o.z), "=f"(o.w) : "l"(a[r][1]));
            __half2 h01 = __floats2half2_rn(o.x, o.y);
            __half2 h23 = __floats2half2_rn(o.z, o.w);
            uint2 u;
            u.x = *(unsigned int*)&h01;
            u.y = *(unsigned int*)&h23;
            outh[(size_t)row * 32 + cg] = u;
        }
    }
}

// ---- gather: warp per node, half-warp per edge (2 in flight), per-edge norm -----
__device__ __forceinline__ float2 h2f(unsigned int h) {
    __half2 hh = *(__half2*)&h;
    return __half22float2(hh);
}

__global__ void __launch_bounds__(256) gather_kernel(const float* __restrict__ bias,
                                                     float* __restrict__ z) {
    const int tid   = threadIdx.x;
    const int lane  = tid & 31;
    const int wid   = tid >> 5;
    const int g     = lane >> 4;   // half-warp id (0/1): edge parity
    const int hl    = lane & 15;   // lane within half-warp -> cols 8*hl..8*hl+7
    const int warpg = (blockIdx.x * 256 + tid) >> 5;
    const int nwarp = gridDim.x * 8;

    const uint4*  __restrict__ xws   = (const uint4*)g_xwh;   // row = 16 uint4
    const float4* __restrict__ bias4 = (const float4*)bias;
    float4*       __restrict__ z4    = (float4*)z;

    const float4 b0 = bias4[2 * hl];
    const float4 b1 = bias4[2 * hl + 1];
    float ls[8], lq[8];
    #pragma unroll
    for (int k = 0; k < 8; k++) { ls[k] = 0.f; lq[k] = 0.f; }

    for (int node = warpg; node < NN; node += nwarp) {
        const int beg = g_start[node];
        const int end = g_cur[node];
        const float di = g_dinv[node];

        // parity-split accumulators break FFMA chains between consecutive edges
        float a[8], a2[8];
        #pragma unroll
        for (int k = 0; k < 8; k++) { a[k] = 0.f; a2[k] = 0.f; }

        // self loop: xwh[node]*dinv[node] (outer *di makes it di^2); half-warp 0
        if (g == 0) {
            uint4 r = __ldcg(&xws[(size_t)node * 16 + hl]);
            float2 p0 = h2f(r.x), p1 = h2f(r.y), p2 = h2f(r.z), p3 = h2f(r.w);
            a[0] += p0.x * di; a[1] += p0.y * di; a[2] += p1.x * di; a[3] += p1.y * di;
            a[4] += p2.x * di; a[5] += p2.y * di; a[6] += p3.x * di; a[7] += p3.y * di;
        }

        for (int base = beg; base < end; base += 32) {
            const int cnt = min(32, end - base);
            unsigned int sv = (lane < cnt) ? g_adj[base + lane] : 0u;  // coalesced
            float dv = __ldg(&g_dinv[sv]);                              // L1-hot 200KB
            #pragma unroll 4
            for (int j = 0; j < cnt; j += 2) {
                int ei = j + g;
                unsigned int sj = __shfl_sync(0xffffffffu, sv, ei & 31);
                float        nj = __shfl_sync(0xffffffffu, dv, ei & 31);
                if (ei < cnt) {
                    uint4 r = __ldcg(&xws[(size_t)sj * 16 + hl]);
                    float2 p0 = h2f(r.x), p1 = h2f(r.y), p2 = h2f(r.z), p3 = h2f(r.w);
                    float* acc = (j & 2) ? a2 : a;
                    acc[0] += p0.x * nj; acc[1] += p0.y * nj;
                    acc[2] += p1.x * nj; acc[3] += p1.y * nj;
                    acc[4] += p2.x * nj; acc[5] += p2.y * nj;
                    acc[6] += p3.x * nj; acc[7] += p3.y * nj;
                }
            }
        }

        // merge parity sets, then combine the two half-warps
        #pragma unroll
        for (int k = 0; k < 8; k++) a[k] += a2[k];
        #pragma unroll
        for (int k = 0; k < 8; k++) a[k] += __shfl_xor_sync(0xffffffffu, a[k], 16);

        if (g == 0) {
            float4 v0, v1;
            v0.x = fmaxf(a[0] * di + b0.x, 0.0f);
            v0.y = fmaxf(a[1] * di + b0.y, 0.0f);
            v0.z = fmaxf(a[2] * di + b0.z, 0.0f);
            v0.w = fmaxf(a[3] * di + b0.w, 0.0f);
            v1.x = fmaxf(a[4] * di + b1.x, 0.0f);
            v1.y = fmaxf(a[5] * di + b1.y, 0.0f);
            v1.z = fmaxf(a[6] * di + b1.z, 0.0f);
            v1.w = fmaxf(a[7] * di + b1.w, 0.0f);
            z4[(size_t)node * 32 + 2 * hl]     = v0;
            z4[(size_t)node * 32 + 2 * hl + 1] = v1;
            ls[0] += v0.x; ls[1] += v0.y; ls[2] += v0.z; ls[3] += v0.w;
            ls[4] += v1.x; ls[5] += v1.y; ls[6] += v1.z; ls[7] += v1.w;
            lq[0] += v0.x * v0.x; lq[1] += v0.y * v0.y; lq[2] += v0.z * v0.z; lq[3] += v0.w * v0.w;
            lq[4] += v1.x * v1.x; lq[5] += v1.y * v1.y; lq[6] += v1.z * v1.z; lq[7] += v1.w * v1.w;
        }
    }

    __shared__ float rs[8][DD];
    __shared__ float rq[8][DD];
    if (g == 0) {
        float4* prs = (float4*)&rs[wid][hl * 8];
        float4* prq = (float4*)&rq[wid][hl * 8];
        prs[0] = make_float4(ls[0], ls[1], ls[2], ls[3]);
        prs[1] = make_float4(ls[4], ls[5], ls[6], ls[7]);
        prq[0] = make_float4(lq[0], lq[1], lq[2], lq[3]);
        prq[1] = make_float4(lq[4], lq[5], lq[6], lq[7]);
    }
    __syncthreads();
    if (tid < DD) {
        float s = 0.f, q = 0.f;
        #pragma unroll
        for (int w = 0; w < 8; w++) { s += rs[w][tid]; q += rq[w][tid]; }
        atomicAdd(&g_sum[tid], s);
        atomicAdd(&g_sumsq[tid], q);
    }
}

// --------- fused BN params + normalize + dropout (params recomputed/block) -------
__global__ void __launch_bounds__(256) final_kernel(const float* __restrict__ gamma,
                                                    const float* __restrict__ beta,
                                                    const float* __restrict__ u,
                                                    float* __restrict__ z) {
    __shared__ float sc[DD], sh[DD];
    const int tid = threadIdx.x;
    if (tid < DD) {
        float mean = g_sum[tid] * (1.0f / NN);
        float var  = g_sumsq[tid] * (1.0f / NN) - mean * mean;
        float s    = gamma[tid] * rsqrtf(var + 1e-5f);
        sc[tid] = s;
        sh[tid] = beta[tid] - mean * s;
    }
    __syncthreads();

    int gid = blockIdx.x * blockDim.x + tid;
    if (gid >= NN * 32) return;
    int j4 = (gid & 31) * 4;

    float4 v  = ((const float4*)z)[gid];
    float4 uu = ((const float4*)u)[gid];
    const float inv_keep = 1.0f / 0.9f;

    float4 r;
    r.x = (uu.x > 0.1f) ? (v.x * sc[j4 + 0] + sh[j4 + 0]) * inv_keep : 0.0f;
    r.y = (uu.y > 0.1f) ? (v.y * sc[j4 + 1] + sh[j4 + 1]) * inv_keep : 0.0f;
    r.z = (uu.z > 0.1f) ? (v.z * sc[j4 + 2] + sh[j4 + 2]) * inv_keep : 0.0f;
    r.w = (uu.w > 0.1f) ? (v.w * sc[j4 + 3] + sh[j4 + 3]) * inv_keep : 0.0f;
    ((float4*)z)[gid] = r;
}

// ----- launch: 5 kernels; submission index 3 = gather (ncu capture target) -------
extern "C" void kernel_launch(void* const* d_in, const int* in_sizes, int n_in,
                              void* d_out, int out_size) {
    const float* x      = (const float*)d_in[0];
    const float* weight = (const float*)d_in[1];
    const float* bias   = (const float*)d_in[2];
    const float* gamma  = (const float*)d_in[3];
    const float* beta   = (const float*)d_in[4];
    const float* drop_u = (const float*)d_in[5];
    const unsigned int* eidx = (const unsigned int*)d_in[6];

    float* z = (float*)d_out;

    static cudaStream_t s2 = nullptr;
    static cudaEvent_t evf = nullptr, evj = nullptr;
    if (s2 == nullptr) {
        cudaStreamCreateWithFlags(&s2, cudaStreamNonBlocking);
        cudaEventCreateWithFlags(&evf, cudaEventDisableTiming);
        cudaEventCreateWithFlags(&evj, cudaEventDisableTiming);
    }

    // [0] fork GEMM (depends only on inputs) -> fp16 xwh directly
    cudaEventRecord(evf, 0);
    cudaStreamWaitEvent(s2, evf, 0);
    gemm_kernel<<<(NN + 31) / 32, 128, 0, s2>>>(x, weight);
    cudaEventRecord(evj, s2);

    // [1][2] main chain: degrees, then fused scan+fill
    deg_kernel<<<(NE + 255) / 256, 256>>>(eidx);
    csr_kernel<<<CSR_G, CSR_B>>>(eidx);

    // [3] join: gather needs CSR + fp16 rows   (ncu captures this one)
    cudaStreamWaitEvent(0, evj, 0);
    gather_kernel<<<592, 256>>>(bias, z);

    // [4] epilogue
    final_kernel<<<(NN * 32 + 255) / 256, 256>>>(gamma, beta, drop_u, z);
}

// round 11
// speedup vs baseline: 1.0375x; 1.0375x over previous
#include <cuda_runtime.h>
#include <cuda_fp16.h>

#define NN 50000
#define NE 600000
#define DD 128
#define PP_G 148
#define PP_B 1024
#define PP_NT (PP_G * PP_B)            // 151552
#define SCAN_G 49                      // ceil(NN/1024)

// ---------------- scratch (static device globals; no allocation) ----------------
__device__ __half g_xwh[NN * DD];               // x @ W fp16, 12.8 MB (L2-resident)
__device__ int    g_degi[NN];                   // zero at load; preproc re-zeroes
__device__ int    g_start[NN];
__device__ int    g_cur[NN];
__device__ unsigned int g_adj[NE];              // src per edge (CSR by dst)
__device__ float  g_dinv[NN];
__device__ int    g_bsum[SCAN_G];
__device__ float  g_sum[DD];                    // zeroed in preproc each run
__device__ float  g_sumsq[DD];
__device__ unsigned int g_count;                // barrier count (self-resets)
__device__ volatile unsigned int g_gen;         // barrier generation (monotonic)

// ---- local int64/int32 detection: values < 50000 => int64 odd words all zero ----
__device__ __forceinline__ int detect_is64(const unsigned int* __restrict__ e) {
    int is64 = 1;
    #pragma unroll
    for (int i = 0; i < 16; i++)
        if (e[2 * i + 1] != 0u) { is64 = 0; break; }
    return is64;
}

// ------ generation-based grid barrier (all PP_G blocks co-resident, 1/SM) --------
__device__ __forceinline__ void grid_sync() {
    __threadfence();
    __syncthreads();
    if (threadIdx.x == 0) {
        unsigned int gen = g_gen;
        if (atomicAdd(&g_count, 1) == PP_G - 1) {
            atomicExch(&g_count, 0);
            __threadfence();
            g_gen = gen + 1;
        } else {
            while (g_gen == gen) __nanosleep(32);
            __threadfence();
        }
    }
    __syncthreads();
}

// ------- preproc: degrees + dinv + prefix scan + adjacency fill, ONE kernel ------
__global__ void __launch_bounds__(PP_B, 1) preproc_kernel(const unsigned int* __restrict__ e) {
    __shared__ int wsums[32];
    __shared__ int bpart[2];
    __shared__ int s64;
    const int tid = threadIdx.x, lane = tid & 31, wid = tid >> 5;
    const int bid = blockIdx.x;
    const int gid = bid * PP_B + tid;

    if (tid == 0) s64 = detect_is64(e);
    if (bid == 0 && tid < DD) { g_sum[tid] = 0.0f; g_sumsq[tid] = 0.0f; }
    __syncthreads();
    const int is64 = s64;

    // ---- phase A: degree atomics (full-machine grid-stride, REDG no-return) ----
    for (int t = gid; t < NE; t += PP_NT) {
        int d = is64 ? (int)((const long long*)e)[NE + t] : ((const int*)e)[NE + t];
        atomicAdd(&g_degi[d], 1);
    }
    grid_sync();

    // ---- phase B: dinv + block-local scan (blocks 0..48 own 1024 nodes each) ----
    const int i = bid * PP_B + tid;   // node index (valid when bid < SCAN_G)
    int d = 0, v = 0;
    if (bid < SCAN_G) {
        d = (i < NN) ? g_degi[i] : 0;
        if (i < NN) g_dinv[i] = rsqrtf((float)d + 1.0f);   // +1 = self loop
        v = d;
        #pragma unroll
        for (int o = 1; o < 32; o <<= 1) {
            int t = __shfl_up_sync(0xffffffffu, v, o);
            if (lane >= o) v += t;
        }
        if (lane == 31) wsums[wid] = v;
        __syncthreads();
        if (wid == 0) {
            int wv = wsums[lane];
            #pragma unroll
            for (int o = 1; o < 32; o <<= 1) {
                int t = __shfl_up_sync(0xffffffffu, wv, o);
                if (lane >= o) wv += t;
            }
            wsums[lane] = wv;
        }
        __syncthreads();
        if (tid == 0) g_bsum[bid] = wsums[31];
    }
    grid_sync();

    // ---- phase C: add predecessor block offsets -> start/cur ----
    if (bid < SCAN_G) {
        if (tid < 64) {
            int t = (tid < bid) ? g_bsum[tid] : 0;
            #pragma unroll
            for (int o = 16; o > 0; o >>= 1) t += __shfl_down_sync(0xffffffffu, t, o);
            if ((tid & 31) == 0) bpart[tid >> 5] = t;
        }
        __syncthreads();
        if (i < NN) {
            int excl = bpart[0] + bpart[1] + (wid > 0 ? wsums[wid - 1] : 0) + (v - d);
            g_start[i] = excl;
            g_cur[i]   = excl;
        }
    }
    grid_sync();

    // ---- phase D: adjacency fill (grid-stride) + re-zero degi for next replay ----
    for (int t = gid; t < NN; t += PP_NT) g_degi[t] = 0;
    for (int t = gid; t < NE; t += PP_NT) {
        int s, dd;
        if (is64) {
            s  = (int)((const long long*)e)[t];
            dd = (int)((const long long*)e)[NE + t];
        } else {
            s  = ((const int*)e)[t];
            dd = ((const int*)e)[NE + t];
        }
        int p = atomicAdd(&g_cur[dd], 1);
        g_adj[p] = (unsigned int)s;
    }
}

// --------- GEMM: g_xwh = fp16(x @ W), packed fma.rn.f32x2, fp16 epilogue ---------
__global__ void __launch_bounds__(128) gemm_kernel(const float* __restrict__ x,
                                                   const float* __restrict__ W) {
    __shared__ unsigned long long xs[32][DD];   // 32 KB
    const int tid = threadIdx.x;
    const int r0  = blockIdx.x * 32;

    for (int idx = tid; idx < 32 * DD; idx += 128) {
        int row = idx >> 7, k = idx & 127;
        float v = (r0 + row < NN) ? x[(size_t)(r0 + row) * DD + k] : 0.0f;
        unsigned int u = __float_as_uint(v);
        xs[row][k] = ((unsigned long long)u << 32) | u;
    }
    __syncthreads();

    const int cg = tid & 31;
    const int rg = tid >> 5;
    unsigned long long a[8][2];
    #pragma unroll
    for (int r = 0; r < 8; r++) { a[r][0] = 0ull; a[r][1] = 0ull; }

    const float4* __restrict__ W4 = (const float4*)W;
    #pragma unroll 4
    for (int k = 0; k < DD; k++) {
        float4 w = W4[k * 32 + cg];
        unsigned long long wxy, wzw;
        asm("mov.b64 %0, {%1,%2};" : "=l"(wxy) : "f"(w.x), "f"(w.y));
        asm("mov.b64 %0, {%1,%2};" : "=l"(wzw) : "f"(w.z), "f"(w.w));
        #pragma unroll
        for (int r = 0; r < 8; r++) {
            unsigned long long xd = xs[rg * 8 + r][k];
            asm("fma.rn.f32x2 %0, %1, %2, %0;" : "+l"(a[r][0]) : "l"(xd), "l"(wxy));
            asm("fma.rn.f32x2 %0, %1, %2, %0;" : "+l"(a[r][1]) : "l"(xd), "l"(wzw));
        }
    }

    uint2* __restrict__ outh = (uint2*)g_xwh;
    #pragma unroll
    for (int r = 0; r < 8; r++) {
        int row = r0 + rg * 8 + r;
        if (row < NN) {
            float4 o;
            asm("mov.b64 {%0,%1}, %2;" : "=f"(o.x), "=f"(o.y) : "l"(a[r][0]));
            asm("mov.b64 {%0,%1}, %2;" : "=f"(o.z), "=f"(o.w) : "l"(a[r][1]));
            __half2 h01 = __floats2half2_rn(o.x, o.y);
            __half2 h23 = __floats2half2_rn(o.z, o.w);
            uint2 u;
            u.x = *(unsigned int*)&h01;
            u.y = *(unsigned int*)&h23;
            outh[(size_t)row * 32 + cg] = u;
        }
    }
}

// ---- gather: warp/node, 2 edges in flight; stats+bias in smem (low regs) --------
__device__ __forceinline__ float2 h2f(unsigned int h) {
    __half2 hh = *(__half2*)&h;
    return __half22float2(hh);
}

__global__ void __launch_bounds__(256, 6) gather_kernel(const float* __restrict__ bias,
                                                        float* __restrict__ z) {
    __shared__ float rs[8][DD];    // per-warp BN sum partials
    __shared__ float rq[8][DD];    // per-warp BN sumsq partials
    __shared__ float sb[DD];       // bias

    const int tid   = threadIdx.x;
    const int lane  = tid & 31;
    const int wid   = tid >> 5;
    const int g     = lane >> 4;   // half-warp id (0/1): edge parity
    const int hl    = lane & 15;   // lane in half-warp -> cols 8*hl..8*hl+7
    const int warpg = (blockIdx.x * 256 + tid) >> 5;
    const int nwarp = gridDim.x * 8;

    if (tid < DD) sb[tid] = bias[tid];
    #pragma unroll
    for (int k = 0; k < 4; k++) {
        rs[wid][lane * 4 + (k & 1) * 0 + 0] = 0.f;  // placeholder, replaced below
    }
    // zero rs/rq: 2048 floats / 256 threads = 8 each
    #pragma unroll
    for (int k = 0; k < 4; k++) {
        ((float*)rs)[tid + k * 256] = 0.f;
        ((float*)rq)[tid + k * 256] = 0.f;
    }
    __syncthreads();

    const uint4* __restrict__ xws = (const uint4*)g_xwh;   // row = 16 uint4
    float4*      __restrict__ z4  = (float4*)z;

    for (int node = warpg; node < NN; node += nwarp) {
        const int beg = g_start[node];
        const int end = g_cur[node];
        const float di = g_dinv[node];

        float a[8];
        #pragma unroll
        for (int k = 0; k < 8; k++) a[k] = 0.f;

        // self loop: xwh[node] * dinv[node] (outer *di makes it di^2); half-warp 0
        if (g == 0) {
            uint4 r = __ldcg(&xws[(size_t)node * 16 + hl]);
            float2 p0 = h2f(r.x), p1 = h2f(r.y), p2 = h2f(r.z), p3 = h2f(r.w);
            a[0] = p0.x * di; a[1] = p0.y * di; a[2] = p1.x * di; a[3] = p1.y * di;
            a[4] = p2.x * di; a[5] = p2.y * di; a[6] = p3.x * di; a[7] = p3.y * di;
        }

        for (int base = beg; base < end; base += 32) {
            const int cnt = min(32, end - base);
            unsigned int sv = (lane < cnt) ? g_adj[base + lane] : 0u;  // coalesced
            float dv = __ldg(&g_dinv[sv]);                              // L1-hot table
            #pragma unroll 4
            for (int j = 0; j < cnt; j += 2) {
                int ei = j + g;
                unsigned int sj = __shfl_sync(0xffffffffu, sv, ei & 31);
                float        nj = __shfl_sync(0xffffffffu, dv, ei & 31);
                if (ei < cnt) {
                    uint4 r = __ldcg(&xws[(size_t)sj * 16 + hl]);
                    float2 p0 = h2f(r.x), p1 = h2f(r.y), p2 = h2f(r.z), p3 = h2f(r.w);
                    a[0] += p0.x * nj; a[1] += p0.y * nj;
                    a[2] += p1.x * nj; a[3] += p1.y * nj;
                    a[4] += p2.x * nj; a[5] += p2.y * nj;
                    a[6] += p3.x * nj; a[7] += p3.y * nj;
                }
            }
        }

        // combine the two half-warps
        #pragma unroll
        for (int k = 0; k < 8; k++) a[k] += __shfl_xor_sync(0xffffffffu, a[k], 16);

        if (g == 0) {
            const int c0 = hl * 8;
            float4 v0, v1;
            v0.x = fmaxf(a[0] * di + sb[c0 + 0], 0.0f);
            v0.y = fmaxf(a[1] * di + sb[c0 + 1], 0.0f);
            v0.z = fmaxf(a[2] * di + sb[c0 + 2], 0.0f);
            v0.w = fmaxf(a[3] * di + sb[c0 + 3], 0.0f);
            v1.x = fmaxf(a[4] * di + sb[c0 + 4], 0.0f);
            v1.y = fmaxf(a[5] * di + sb[c0 + 5], 0.0f);
            v1.z = fmaxf(a[6] * di + sb[c0 + 6], 0.0f);
            v1.w = fmaxf(a[7] * di + sb[c0 + 7], 0.0f);
            z4[(size_t)node * 32 + 2 * hl]     = v0;
            z4[(size_t)node * 32 + 2 * hl + 1] = v1;
            // BN partials in smem (each lane owns its 8 columns of rs[wid])
            rs[wid][c0 + 0] += v0.x; rq[wid][c0 + 0] += v0.x * v0.x;
            rs[wid][c0 + 1] += v0.y; rq[wid][c0 + 1] += v0.y * v0.y;
            rs[wid][c0 + 2] += v0.z; rq[wid][c0 + 2] += v0.z * v0.z;
            rs[wid][c0 + 3] += v0.w; rq[wid][c0 + 3] += v0.w * v0.w;
            rs[wid][c0 + 4] += v1.x; rq[wid][c0 + 4] += v1.x * v1.x;
            rs[wid][c0 + 5] += v1.y; rq[wid][c0 + 5] += v1.y * v1.y;
            rs[wid][c0 + 6] += v1.z; rq[wid][c0 + 6] += v1.z * v1.z;
            rs[wid][c0 + 7] += v1.w; rq[wid][c0 + 7] += v1.w * v1.w;
        }
    }

    __syncthreads();
    if (tid < DD) {
        float s = 0.f, q = 0.f;
        #pragma unroll
        for (int w = 0; w < 8; w++) { s += rs[w][tid]; q += rq[w][tid]; }
        atomicAdd(&g_sum[tid], s);
        atomicAdd(&g_sumsq[tid], q);
    }
}

// --------- fused BN params + normalize + dropout (params recomputed/block) -------
__global__ void __launch_bounds__(256) final_kernel(const float* __restrict__ gamma,
                                                    const float* __restrict__ beta,
                                                    const float* __restrict__ u,
                                                    float* __restrict__ z) {
    __shared__ float sc[DD], sh[DD];
    const int tid = threadIdx.x;
    if (tid < DD) {
        float mean = g_sum[tid] * (1.0f / NN);
        float var  = g_sumsq[tid] * (1.0f / NN) - mean * mean;
        float s    = gamma[tid] * rsqrtf(var + 1e-5f);
        sc[tid] = s;
        sh[tid] = beta[tid] - mean * s;
    }
    __syncthreads();

    int gid = blockIdx.x * blockDim.x + tid;
    if (gid >= NN * 32) return;
    int j4 = (gid & 31) * 4;

    float4 v  = ((const float4*)z)[gid];
    float4 uu = ((const float4*)u)[gid];
    const float inv_keep = 1.0f / 0.9f;

    float4 r;
    r.x = (uu.x > 0.1f) ? (v.x * sc[j4 + 0] + sh[j4 + 0]) * inv_keep : 0.0f;
    r.y = (uu.y > 0.1f) ? (v.y * sc[j4 + 1] + sh[j4 + 1]) * inv_keep : 0.0f;
    r.z = (uu.z > 0.1f) ? (v.z * sc[j4 + 2] + sh[j4 + 2]) * inv_keep : 0.0f;
    r.w = (uu.w > 0.1f) ? (v.w * sc[j4 + 3] + sh[j4 + 3]) * inv_keep : 0.0f;
    ((float4*)z)[gid] = r;
}

// ---------------- launch: 4 kernels; GEMM concurrent with preproc ----------------
extern "C" void kernel_launch(void* const* d_in, const int* in_sizes, int n_in,
                              void* d_out, int out_size) {
    const float* x      = (const float*)d_in[0];
    const float* weight = (const float*)d_in[1];
    const float* bias   = (const float*)d_in[2];
    const float* gamma  = (const float*)d_in[3];
    const float* beta   = (const float*)d_in[4];
    const float* drop_u = (const float*)d_in[5];
    const unsigned int* eidx = (const unsigned int*)d_in[6];

    float* z = (float*)d_out;

    static cudaStream_t s2 = nullptr;
    static cudaEvent_t evf = nullptr, evj = nullptr;
    if (s2 == nullptr) {
        cudaStreamCreateWithFlags(&s2, cudaStreamNonBlocking);
        cudaEventCreateWithFlags(&evf, cudaEventDisableTiming);
        cudaEventCreateWithFlags(&evj, cudaEventDisableTiming);
    }

    // [0] GEMM on side stream (depends only on inputs)
    cudaEventRecord(evf, 0);
    cudaStreamWaitEvent(s2, evf, 0);
    gemm_kernel<<<(NN + 31) / 32, 128, 0, s2>>>(x, weight);
    cudaEventRecord(evj, s2);

    // [1] fused preproc: deg + scan + fill (concurrent with GEMM)
    preproc_kernel<<<PP_G, PP_B>>>(eidx);

    // [2] gather needs CSR + fp16 rows
    cudaStreamWaitEvent(0, evj, 0);
    gather_kernel<<<888, 256>>>(bias, z);

    // [3] epilogue
    final_kernel<<<(NN * 32 + 255) / 256, 256>>>(gamma, beta, drop_u, z);
}

// round 12
// speedup vs baseline: 1.1042x; 1.0642x over previous
#include <cuda_runtime.h>
#include <cuda_fp16.h>

#define NN 50000
#define NE 600000
#define DD 128
#define SCAN_B 1024
#define SCAN_G ((NN + SCAN_B - 1) / SCAN_B)   // 49

// ---------------- scratch (static device globals; no allocation) ----------------
__device__ __half g_xwh[NN * DD];               // x @ W fp16, 12.8 MB (L2-resident)
__device__ int    g_degi[NN];                   // zero at load; fill re-zeroes
__device__ int    g_start[NN];
__device__ int    g_cur[NN];
__device__ unsigned int g_adj[NE];              // src per edge (CSR by dst)
__device__ float  g_dinv[NN];
__device__ int    g_bsum[SCAN_G];
__device__ unsigned int g_ready;                // scanf sync; fill resets to 0
__device__ float  g_sum[DD];                    // zeroed in scanf each run
__device__ float  g_sumsq[DD];
__device__ unsigned int g_mask[(NN * DD) / 32]; // dropout keep-bits, 800 KB

// ---- local int64/int32 detection: values < 50000 => int64 odd words all zero ----
__device__ __forceinline__ int detect_is64(const unsigned int* __restrict__ e) {
    int is64 = 1;
    #pragma unroll
    for (int i = 0; i < 16; i++)
        if (e[2 * i + 1] != 0u) { is64 = 0; break; }
    return is64;
}

// ---------------- degree over dst ----------------
__global__ void deg_kernel(const unsigned int* __restrict__ e) {
    __shared__ int s64;
    if (threadIdx.x == 0) s64 = detect_is64(e);
    __syncthreads();
    int t = blockIdx.x * blockDim.x + threadIdx.x;
    if (t >= NE) return;
    int d;
    if (s64) d = (int)((const long long*)e)[NE + t];
    else     d = ((const int*)e)[NE + t];
    atomicAdd(&g_degi[d], 1);
}

// ------- fused scan: dinv + block scan + cross-block sync + start/cur ------------
// 49 blocks, all co-resident (<=148 SMs) -> spin cannot deadlock.
// g_ready is 0 on entry (static init / reset by fill in the previous run).
__global__ void __launch_bounds__(SCAN_B) scanf_kernel() {
    __shared__ int wsums[32];
    __shared__ int bpart[2];
    const int tid = threadIdx.x, lane = tid & 31, wid = tid >> 5;
    const int bid = blockIdx.x;

    if (bid == 0 && tid < DD) { g_sum[tid] = 0.0f; g_sumsq[tid] = 0.0f; }

    const int i = bid * SCAN_B + tid;
    int d = (i < NN) ? g_degi[i] : 0;
    if (i < NN) g_dinv[i] = rsqrtf((float)d + 1.0f);   // +1 = self loop

    int v = d;
    #pragma unroll
    for (int o = 1; o < 32; o <<= 1) {
        int t = __shfl_up_sync(0xffffffffu, v, o);
        if (lane >= o) v += t;
    }
    if (lane == 31) wsums[wid] = v;
    __syncthreads();
    if (wid == 0) {
        int wv = wsums[lane];
        #pragma unroll
        for (int o = 1; o < 32; o <<= 1) {
            int t = __shfl_up_sync(0xffffffffu, wv, o);
            if (lane >= o) wv += t;
        }
        wsums[lane] = wv;
    }
    __syncthreads();

    if (tid == 0) {
        g_bsum[bid] = wsums[31];
        __threadfence();
        atomicAdd(&g_ready, 1u);
        volatile unsigned int* r = &g_ready;
        while (*r < (unsigned)SCAN_G) __nanosleep(32);
        __threadfence();
    }
    __syncthreads();

    if (tid < 64) {
        int t = (tid < bid) ? g_bsum[tid] : 0;
        #pragma unroll
        for (int o = 16; o > 0; o >>= 1) t += __shfl_down_sync(0xffffffffu, t, o);
        if ((tid & 31) == 0) bpart[tid >> 5] = t;
    }
    __syncthreads();

    if (i < NN) {
        int excl = bpart[0] + bpart[1] + (wid > 0 ? wsums[wid - 1] : 0) + (v - d);
        g_start[i] = excl;
        g_cur[i]   = excl;
    }
}

// -------- adjacency fill; re-zero degi + reset scan sync for next replay ---------
__global__ void fill_kernel(const unsigned int* __restrict__ e) {
    __shared__ int s64;
    if (threadIdx.x == 0) s64 = detect_is64(e);
    __syncthreads();
    int t = blockIdx.x * blockDim.x + threadIdx.x;
    if (t >= NE) return;
    if (t < NN) g_degi[t] = 0;                 // scanf (last reader) already ran
    if (t == 0) g_ready = 0u;                  // reset for next run's scanf
    int s, d;
    if (s64) {
        s = (int)((const long long*)e)[t];
        d = (int)((const long long*)e)[NE + t];
    } else {
        s = ((const int*)e)[t];
        d = ((const int*)e)[NE + t];
    }
    int p = atomicAdd(&g_cur[d], 1);
    g_adj[p] = (unsigned int)s;
}

// --------- GEMM: g_xwh = fp16(x @ W), packed fma.rn.f32x2, fp16 epilogue ---------
__global__ void __launch_bounds__(128) gemm_kernel(const float* __restrict__ x,
                                                   const float* __restrict__ W) {
    __shared__ unsigned long long xs[32][DD];   // 32 KB
    const int tid = threadIdx.x;
    const int r0  = blockIdx.x * 32;

    for (int idx = tid; idx < 32 * DD; idx += 128) {
        int row = idx >> 7, k = idx & 127;
        float v = (r0 + row < NN) ? x[(size_t)(r0 + row) * DD + k] : 0.0f;
        unsigned int u = __float_as_uint(v);
        xs[row][k] = ((unsigned long long)u << 32) | u;
    }
    __syncthreads();

    const int cg = tid & 31;
    const int rg = tid >> 5;
    unsigned long long a[8][2];
    #pragma unroll
    for (int r = 0; r < 8; r++) { a[r][0] = 0ull; a[r][1] = 0ull; }

    const float4* __restrict__ W4 = (const float4*)W;
    #pragma unroll 4
    for (int k = 0; k < DD; k++) {
        float4 w = W4[k * 32 + cg];
        unsigned long long wxy, wzw;
        asm("mov.b64 %0, {%1,%2};" : "=l"(wxy) : "f"(w.x), "f"(w.y));
        asm("mov.b64 %0, {%1,%2};" : "=l"(wzw) : "f"(w.z), "f"(w.w));
        #pragma unroll
        for (int r = 0; r < 8; r++) {
            unsigned long long xd = xs[rg * 8 + r][k];
            asm("fma.rn.f32x2 %0, %1, %2, %0;" : "+l"(a[r][0]) : "l"(xd), "l"(wxy));
            asm("fma.rn.f32x2 %0, %1, %2, %0;" : "+l"(a[r][1]) : "l"(xd), "l"(wzw));
        }
    }

    uint2* __restrict__ outh = (uint2*)g_xwh;
    #pragma unroll
    for (int r = 0; r < 8; r++) {
        int row = r0 + rg * 8 + r;
        if (row < NN) {
            float4 o;
            asm("mov.b64 {%0,%1}, %2;" : "=f"(o.x), "=f"(o.y) : "l"(a[r][0]));
            asm("mov.b64 {%0,%1}, %2;" : "=f"(o.z), "=f"(o.w) : "l"(a[r][1]));
            __half2 h01 = __floats2half2_rn(o.x, o.y);
            __half2 h23 = __floats2half2_rn(o.z, o.w);
            uint2 u;
            u.x = *(unsigned int*)&h01;
            u.y = *(unsigned int*)&h23;
            outh[(size_t)row * 32 + cg] = u;
        }
    }
}

// ------------- dropout keep-bit mask: 1 bit per element via warp ballot ----------
__global__ void __launch_bounds__(256) mask_kernel(const float* __restrict__ u) {
    int i = blockIdx.x * blockDim.x + threadIdx.x;   // NN*DD = 6.4M, exact multiple
    unsigned int b = __ballot_sync(0xffffffffu, u[i] > 0.1f);
    if ((threadIdx.x & 31) == 0) g_mask[i >> 5] = b;
}

// ---- gather: warp/node, 2 edges in flight; stats+bias in smem (low regs) --------
__device__ __forceinline__ float2 h2f(unsigned int h) {
    __half2 hh = *(__half2*)&h;
    return __half22float2(hh);
}

__global__ void __launch_bounds__(256, 6) gather_kernel(const float* __restrict__ bias,
                                                        float* __restrict__ z) {
    __shared__ float rs[8][DD];    // per-warp BN sum partials
    __shared__ float rq[8][DD];    // per-warp BN sumsq partials
    __shared__ float sb[DD];       // bias

    const int tid   = threadIdx.x;
    const int lane  = tid & 31;
    const int wid   = tid >> 5;
    const int g     = lane >> 4;   // half-warp id (0/1): edge parity
    const int hl    = lane & 15;   // lane in half-warp -> cols 8*hl..8*hl+7
    const int warpg = (blockIdx.x * 256 + tid) >> 5;
    const int nwarp = gridDim.x * 8;

    if (tid < DD) sb[tid] = bias[tid];
    #pragma unroll
    for (int k = 0; k < 4; k++) {
        ((float*)rs)[tid + k * 256] = 0.f;
        ((float*)rq)[tid + k * 256] = 0.f;
    }
    __syncthreads();

    const uint4* __restrict__ xws = (const uint4*)g_xwh;   // row = 16 uint4
    float4*      __restrict__ z4  = (float4*)z;

    for (int node = warpg; node < NN; node += nwarp) {
        const int beg = g_start[node];
        const int end = g_cur[node];
        const float di = g_dinv[node];

        float a[8];
        #pragma unroll
        for (int k = 0; k < 8; k++) a[k] = 0.f;

        // self loop: xwh[node] * dinv[node] (outer *di makes it di^2); half-warp 0
        if (g == 0) {
            uint4 r = __ldcg(&xws[(size_t)node * 16 + hl]);
            float2 p0 = h2f(r.x), p1 = h2f(r.y), p2 = h2f(r.z), p3 = h2f(r.w);
            a[0] = p0.x * di; a[1] = p0.y * di; a[2] = p1.x * di; a[3] = p1.y * di;
            a[4] = p2.x * di; a[5] = p2.y * di; a[6] = p3.x * di; a[7] = p3.y * di;
        }

        for (int base = beg; base < end; base += 32) {
            const int cnt = min(32, end - base);
            unsigned int sv = (lane < cnt) ? g_adj[base + lane] : 0u;  // coalesced
            float dv = __ldg(&g_dinv[sv]);                              // L1-hot table
            #pragma unroll 4
            for (int j = 0; j < cnt; j += 2) {
                int ei = j + g;
                unsigned int sj = __shfl_sync(0xffffffffu, sv, ei & 31);
                float        nj = __shfl_sync(0xffffffffu, dv, ei & 31);
                if (ei < cnt) {
                    uint4 r = __ldcg(&xws[(size_t)sj * 16 + hl]);
                    float2 p0 = h2f(r.x), p1 = h2f(r.y), p2 = h2f(r.z), p3 = h2f(r.w);
                    a[0] += p0.x * nj; a[1] += p0.y * nj;
                    a[2] += p1.x * nj; a[3] += p1.y * nj;
                    a[4] += p2.x * nj; a[5] += p2.y * nj;
                    a[6] += p3.x * nj; a[7] += p3.y * nj;
                }
            }
        }

        // combine the two half-warps
        #pragma unroll
        for (int k = 0; k < 8; k++) a[k] += __shfl_xor_sync(0xffffffffu, a[k], 16);

        if (g == 0) {
            const int c0 = hl * 8;
            float4 v0, v1;
            v0.x = fmaxf(a[0] * di + sb[c0 + 0], 0.0f);
            v0.y = fmaxf(a[1] * di + sb[c0 + 1], 0.0f);
            v0.z = fmaxf(a[2] * di + sb[c0 + 2], 0.0f);
            v0.w = fmaxf(a[3] * di + sb[c0 + 3], 0.0f);
            v1.x = fmaxf(a[4] * di + sb[c0 + 4], 0.0f);
            v1.y = fmaxf(a[5] * di + sb[c0 + 5], 0.0f);
            v1.z = fmaxf(a[6] * di + sb[c0 + 6], 0.0f);
            v1.w = fmaxf(a[7] * di + sb[c0 + 7], 0.0f);
            z4[(size_t)node * 32 + 2 * hl]     = v0;
            z4[(size_t)node * 32 + 2 * hl + 1] = v1;
            rs[wid][c0 + 0] += v0.x; rq[wid][c0 + 0] += v0.x * v0.x;
            rs[wid][c0 + 1] += v0.y; rq[wid][c0 + 1] += v0.y * v0.y;
            rs[wid][c0 + 2] += v0.z; rq[wid][c0 + 2] += v0.z * v0.z;
            rs[wid][c0 + 3] += v0.w; rq[wid][c0 + 3] += v0.w * v0.w;
            rs[wid][c0 + 4] += v1.x; rq[wid][c0 + 4] += v1.x * v1.x;
            rs[wid][c0 + 5] += v1.y; rq[wid][c0 + 5] += v1.y * v1.y;
            rs[wid][c0 + 6] += v1.z; rq[wid][c0 + 6] += v1.z * v1.z;
            rs[wid][c0 + 7] += v1.w; rq[wid][c0 + 7] += v1.w * v1.w;
        }
    }

    __syncthreads();
    if (tid < DD) {
        float s = 0.f, q = 0.f;
        #pragma unroll
        for (int w = 0; w < 8; w++) { s += rs[w][tid]; q += rq[w][tid]; }
        atomicAdd(&g_sum[tid], s);
        atomicAdd(&g_sumsq[tid], q);
    }
}

// --------- fused BN params + normalize + dropout (bitmask, not u) ----------------
__global__ void __launch_bounds__(256) final_kernel(const float* __restrict__ gamma,
                                                    const float* __restrict__ beta,
                                                    float* __restrict__ z) {
    __shared__ float sc[DD], sh[DD];
    const int tid = threadIdx.x;
    if (tid < DD) {
        float mean = g_sum[tid] * (1.0f / NN);
        float var  = g_sumsq[tid] * (1.0f / NN) - mean * mean;
        float s    = gamma[tid] * rsqrtf(var + 1e-5f);
        sc[tid] = s;
        sh[tid] = beta[tid] - mean * s;
    }
    __syncthreads();

    int gid = blockIdx.x * blockDim.x + tid;
    if (gid >= NN * 32) return;
    int j4 = (gid & 31) * 4;

    float4 v = __ldcg(&((const float4*)z)[gid]);
    unsigned int m = g_mask[gid >> 3] >> ((gid & 7) * 4);   // 4 keep-bits
    const float inv_keep = 1.0f / 0.9f;

    float4 r;
    r.x = (m & 1u) ? (v.x * sc[j4 + 0] + sh[j4 + 0]) * inv_keep : 0.0f;
    r.y = (m & 2u) ? (v.y * sc[j4 + 1] + sh[j4 + 1]) * inv_keep : 0.0f;
    r.z = (m & 4u) ? (v.z * sc[j4 + 2] + sh[j4 + 2]) * inv_keep : 0.0f;
    r.w = (m & 8u) ? (v.w * sc[j4 + 3] + sh[j4 + 3]) * inv_keep : 0.0f;
    ((float4*)z)[gid] = r;
}

// ------- launch: gemm ∥ mask ∥ (deg -> scanf -> fill) -> gather -> final ---------
extern "C" void kernel_launch(void* const* d_in, const int* in_sizes, int n_in,
                              void* d_out, int out_size) {
    const float* x      = (const float*)d_in[0];
    const float* weight = (const float*)d_in[1];
    const float* bias   = (const float*)d_in[2];
    const float* gamma  = (const float*)d_in[3];
    const float* beta   = (const float*)d_in[4];
    const float* drop_u = (const float*)d_in[5];
    const unsigned int* eidx = (const unsigned int*)d_in[6];

    float* z = (float*)d_out;

    static cudaStream_t s2 = nullptr, s3 = nullptr;
    static cudaEvent_t evf = nullptr, evj = nullptr, evm = nullptr;
    if (s2 == nullptr) {
        cudaStreamCreateWithFlags(&s2, cudaStreamNonBlocking);
        cudaStreamCreateWithFlags(&s3, cudaStreamNonBlocking);
        cudaEventCreateWithFlags(&evf, cudaEventDisableTiming);
        cudaEventCreateWithFlags(&evj, cudaEventDisableTiming);
        cudaEventCreateWithFlags(&evm, cudaEventDisableTiming);
    }

    // fork: GEMM (s2) and dropout-mask (s3) depend only on inputs
    cudaEventRecord(evf, 0);
    cudaStreamWaitEvent(s2, evf, 0);
    cudaStreamWaitEvent(s3, evf, 0);
    gemm_kernel<<<(NN + 31) / 32, 128, 0, s2>>>(x, weight);
    cudaEventRecord(evj, s2);
    mask_kernel<<<(NN * DD) / 256, 256, 0, s3>>>(drop_u);
    cudaEventRecord(evm, s3);

    // main chain: edge preprocessing
    deg_kernel<<<(NE + 255) / 256, 256>>>(eidx);
    scanf_kernel<<<SCAN_G, SCAN_B>>>();
    fill_kernel<<<(NE + 255) / 256, 256>>>(eidx);

    // join: gather needs CSR + fp16 rows
    cudaStreamWaitEvent(0, evj, 0);
    gather_kernel<<<888, 256>>>(bias, z);

    // epilogue needs BN stats + mask
    cudaStreamWaitEvent(0, evm, 0);
    final_kernel<<<(NN * 32 + 255) / 256, 256>>>(gamma, beta, z);
}

// round 13
// speedup vs baseline: 1.1056x; 1.0013x over previous
#include <cuda_runtime.h>
#include <cuda_fp16.h>

#define NN 50000
#define NE 600000
#define DD 128
#define SCAN_B 1024
#define SCAN_G ((NN + SCAN_B - 1) / SCAN_B)   // 49

// ---------------- scratch (static device globals; no allocation) ----------------
__device__ float  g_xw[NN * DD];                // x @ W fp32, 25.6 MB
__device__ __half g_xwh[NN * DD];               // dinv[s] * (x@W)[s] fp16, 12.8 MB
__device__ int    g_degi[NN];                   // zero at load; fill re-zeroes
__device__ int    g_start[NN];
__device__ int    g_cur[NN];
__device__ unsigned int g_adj[NE];              // src per edge (CSR by dst)
__device__ float  g_dinv[NN];
__device__ int    g_bsum[SCAN_G];
__device__ unsigned int g_ready;                // scanf sync; fill resets to 0
__device__ float  g_sum[DD];                    // zeroed in scanf each run
__device__ float  g_sumsq[DD];
__device__ unsigned int g_mask[(NN * DD) / 32]; // dropout keep-bits, 800 KB

// ---- local int64/int32 detection: values < 50000 => int64 odd words all zero ----
__device__ __forceinline__ int detect_is64(const unsigned int* __restrict__ e) {
    int is64 = 1;
    #pragma unroll
    for (int i = 0; i < 16; i++)
        if (e[2 * i + 1] != 0u) { is64 = 0; break; }
    return is64;
}

// ---------------- degree over dst ----------------
__global__ void deg_kernel(const unsigned int* __restrict__ e) {
    __shared__ int s64;
    if (threadIdx.x == 0) s64 = detect_is64(e);
    __syncthreads();
    int t = blockIdx.x * blockDim.x + threadIdx.x;
    if (t >= NE) return;
    int d;
    if (s64) d = (int)((const long long*)e)[NE + t];
    else     d = ((const int*)e)[NE + t];
    atomicAdd(&g_degi[d], 1);
}

// ------- fused scan: dinv + block scan + cross-block sync + start/cur ------------
// 49 blocks, all co-resident (<=148 SMs) -> spin cannot deadlock.
// g_ready is 0 on entry (static init / reset by fill in the previous run).
__global__ void __launch_bounds__(SCAN_B) scanf_kernel() {
    __shared__ int wsums[32];
    __shared__ int bpart[2];
    const int tid = threadIdx.x, lane = tid & 31, wid = tid >> 5;
    const int bid = blockIdx.x;

    if (bid == 0 && tid < DD) { g_sum[tid] = 0.0f; g_sumsq[tid] = 0.0f; }

    const int i = bid * SCAN_B + tid;
    int d = (i < NN) ? g_degi[i] : 0;
    if (i < NN) g_dinv[i] = rsqrtf((float)d + 1.0f);   // +1 = self loop

    int v = d;
    #pragma unroll
    for (int o = 1; o < 32; o <<= 1) {
        int t = __shfl_up_sync(0xffffffffu, v, o);
        if (lane >= o) v += t;
    }
    if (lane == 31) wsums[wid] = v;
    __syncthreads();
    if (wid == 0) {
        int wv = wsums[lane];
        #pragma unroll
        for (int o = 1; o < 32; o <<= 1) {
            int t = __shfl_up_sync(0xffffffffu, wv, o);
            if (lane >= o) wv += t;
        }
        wsums[lane] = wv;
    }
    __syncthreads();

    if (tid == 0) {
        g_bsum[bid] = wsums[31];
        __threadfence();
        atomicAdd(&g_ready, 1u);
        volatile unsigned int* r = &g_ready;
        while (*r < (unsigned)SCAN_G) __nanosleep(32);
        __threadfence();
    }
    __syncthreads();

    if (tid < 64) {
        int t = (tid < bid) ? g_bsum[tid] : 0;
        #pragma unroll
        for (int o = 16; o > 0; o >>= 1) t += __shfl_down_sync(0xffffffffu, t, o);
        if ((tid & 31) == 0) bpart[tid >> 5] = t;
    }
    __syncthreads();

    if (i < NN) {
        int excl = bpart[0] + bpart[1] + (wid > 0 ? wsums[wid - 1] : 0) + (v - d);
        g_start[i] = excl;
        g_cur[i]   = excl;
    }
}

// -------- adjacency fill; re-zero degi + reset scan sync for next replay ---------
__global__ void fill_kernel(const unsigned int* __restrict__ e) {
    __shared__ int s64;
    if (threadIdx.x == 0) s64 = detect_is64(e);
    __syncthreads();
    int t = blockIdx.x * blockDim.x + threadIdx.x;
    if (t >= NE) return;
    if (t < NN) g_degi[t] = 0;                 // scanf (last reader) already ran
    if (t == 0) g_ready = 0u;                  // reset for next run's scanf
    int s, d;
    if (s64) {
        s = (int)((const long long*)e)[t];
        d = (int)((const long long*)e)[NE + t];
    } else {
        s = ((const int*)e)[t];
        d = ((const int*)e)[NE + t];
    }
    int p = atomicAdd(&g_cur[d], 1);
    g_adj[p] = (unsigned int)s;
}

// ---------------- GEMM: g_xw = x @ W (fp32), packed fma.rn.f32x2 -----------------
__global__ void __launch_bounds__(128) gemm_kernel(const float* __restrict__ x,
                                                   const float* __restrict__ W) {
    __shared__ unsigned long long xs[32][DD];   // 32 KB
    const int tid = threadIdx.x;
    const int r0  = blockIdx.x * 32;

    for (int idx = tid; idx < 32 * DD; idx += 128) {
        int row = idx >> 7, k = idx & 127;
        float v = (r0 + row < NN) ? x[(size_t)(r0 + row) * DD + k] : 0.0f;
        unsigned int u = __float_as_uint(v);
        xs[row][k] = ((unsigned long long)u << 32) | u;
    }
    __syncthreads();

    const int cg = tid & 31;
    const int rg = tid >> 5;
    unsigned long long a[8][2];
    #pragma unroll
    for (int r = 0; r < 8; r++) { a[r][0] = 0ull; a[r][1] = 0ull; }

    const float4* __restrict__ W4 = (const float4*)W;
    #pragma unroll 4
    for (int k = 0; k < DD; k++) {
        float4 w = W4[k * 32 + cg];
        unsigned long long wxy, wzw;
        asm("mov.b64 %0, {%1,%2};" : "=l"(wxy) : "f"(w.x), "f"(w.y));
        asm("mov.b64 %0, {%1,%2};" : "=l"(wzw) : "f"(w.z), "f"(w.w));
        #pragma unroll
        for (int r = 0; r < 8; r++) {
            unsigned long long xd = xs[rg * 8 + r][k];
            asm("fma.rn.f32x2 %0, %1, %2, %0;" : "+l"(a[r][0]) : "l"(xd), "l"(wxy));
            asm("fma.rn.f32x2 %0, %1, %2, %0;" : "+l"(a[r][1]) : "l"(xd), "l"(wzw));
        }
    }

    float4* __restrict__ out4 = (float4*)g_xw;
    #pragma unroll
    for (int r = 0; r < 8; r++) {
        int row = r0 + rg * 8 + r;
        if (row < NN) {
            float4 o;
            asm("mov.b64 {%0,%1}, %2;" : "=f"(o.x), "=f"(o.y) : "l"(a[r][0]));
            asm("mov.b64 {%0,%1}, %2;" : "=f"(o.z), "=f"(o.w) : "l"(a[r][1]));
            out4[(size_t)row * 32 + cg] = o;
        }
    }
}

// ------------- prescale: g_xwh[row] = fp16(dinv[row] * g_xw[row]) ----------------
__global__ void __launch_bounds__(256) prescale_kernel() {
    int gid = blockIdx.x * blockDim.x + threadIdx.x;   // NN*32 float4 chunks
    if (gid >= NN * 32) return;
    float di = g_dinv[gid >> 5];
    float4 v = ((const float4*)g_xw)[gid];
    __half2 h01 = __floats2half2_rn(v.x * di, v.y * di);
    __half2 h23 = __floats2half2_rn(v.z * di, v.w * di);
    uint2 u;
    u.x = *(unsigned int*)&h01;
    u.y = *(unsigned int*)&h23;
    ((uint2*)g_xwh)[gid] = u;
}

// ------------- dropout keep-bit mask: 1 bit per element via warp ballot ----------
__global__ void __launch_bounds__(256) mask_kernel(const float* __restrict__ u) {
    int i = blockIdx.x * blockDim.x + threadIdx.x;   // NN*DD = 6.4M, exact multiple
    unsigned int b = __ballot_sync(0xffffffffu, u[i] > 0.1f);
    if ((threadIdx.x & 31) == 0) g_mask[i >> 5] = b;
}

// ---- gather (measured best): warp per node, 2 edges in flight, fp16 rows --------
__device__ __forceinline__ float2 h2f(unsigned int h) {
    __half2 hh = *(__half2*)&h;
    return __half22float2(hh);
}

__global__ void __launch_bounds__(256) gather_kernel(const float* __restrict__ bias,
                                                     float* __restrict__ z) {
    const int tid   = threadIdx.x;
    const int lane  = tid & 31;
    const int wid   = tid >> 5;
    const int g     = lane >> 4;   // half-warp id (0/1)
    const int hl    = lane & 15;   // lane within half-warp -> cols 8*hl..8*hl+7
    const int warpg = (blockIdx.x * 256 + tid) >> 5;
    const int nwarp = gridDim.x * 8;

    const uint4*  __restrict__ xws   = (const uint4*)g_xwh;   // row = 16 uint4
    const float4* __restrict__ bias4 = (const float4*)bias;
    float4*       __restrict__ z4    = (float4*)z;

    const float4 b0 = bias4[2 * hl];
    const float4 b1 = bias4[2 * hl + 1];
    float ls[8], lq[8];
    #pragma unroll
    for (int k = 0; k < 8; k++) { ls[k] = 0.f; lq[k] = 0.f; }

    for (int node = warpg; node < NN; node += nwarp) {
        const int beg = g_start[node];
        const int end = g_cur[node];
        const float di = g_dinv[node];

        float a[8];
        #pragma unroll
        for (int k = 0; k < 8; k++) a[k] = 0.f;

        // self loop (only half-warp 0 adds it)
        if (g == 0) {
            uint4 r = __ldcg(&xws[(size_t)node * 16 + hl]);
            float2 p0 = h2f(r.x), p1 = h2f(r.y), p2 = h2f(r.z), p3 = h2f(r.w);
            a[0] += p0.x; a[1] += p0.y; a[2] += p1.x; a[3] += p1.y;
            a[4] += p2.x; a[5] += p2.y; a[6] += p3.x; a[7] += p3.y;
        }

        for (int base = beg; base < end; base += 32) {
            const int cnt = min(32, end - base);
            unsigned int sv = (lane < cnt) ? g_adj[base + lane] : 0u;  // coalesced
            #pragma unroll 4
            for (int j = 0; j < cnt; j += 2) {
                int ei = j + g;
                unsigned int sj = __shfl_sync(0xffffffffu, sv, ei & 31);
                if (ei < cnt) {
                    uint4 r = __ldcg(&xws[(size_t)sj * 16 + hl]);
                    float2 p0 = h2f(r.x), p1 = h2f(r.y), p2 = h2f(r.z), p3 = h2f(r.w);
                    a[0] += p0.x; a[1] += p0.y; a[2] += p1.x; a[3] += p1.y;
                    a[4] += p2.x; a[5] += p2.y; a[6] += p3.x; a[7] += p3.y;
                }
            }
        }

        // combine the two half-warps
        #pragma unroll
        for (int k = 0; k < 8; k++) a[k] += __shfl_xor_sync(0xffffffffu, a[k], 16);

        if (g == 0) {
            float4 v0, v1;
            v0.x = fmaxf(a[0] * di + b0.x, 0.0f);
            v0.y = fmaxf(a[1] * di + b0.y, 0.0f);
            v0.z = fmaxf(a[2] * di + b0.z, 0.0f);
            v0.w = fmaxf(a[3] * di + b0.w, 0.0f);
            v1.x = fmaxf(a[4] * di + b1.x, 0.0f);
            v1.y = fmaxf(a[5] * di + b1.y, 0.0f);
            v1.z = fmaxf(a[6] * di + b1.z, 0.0f);
            v1.w = fmaxf(a[7] * di + b1.w, 0.0f);
            z4[(size_t)node * 32 + 2 * hl]     = v0;
            z4[(size_t)node * 32 + 2 * hl + 1] = v1;
            ls[0] += v0.x; ls[1] += v0.y; ls[2] += v0.z; ls[3] += v0.w;
            ls[4] += v1.x; ls[5] += v1.y; ls[6] += v1.z; ls[7] += v1.w;
            lq[0] += v0.x * v0.x; lq[1] += v0.y * v0.y; lq[2] += v0.z * v0.z; lq[3] += v0.w * v0.w;
            lq[4] += v1.x * v1.x; lq[5] += v1.y * v1.y; lq[6] += v1.z * v1.z; lq[7] += v1.w * v1.w;
        }
    }

    __shared__ float rs[8][DD];
    __shared__ float rq[8][DD];
    if (g == 0) {
        float4* prs = (float4*)&rs[wid][hl * 8];
        float4* prq = (float4*)&rq[wid][hl * 8];
        prs[0] = make_float4(ls[0], ls[1], ls[2], ls[3]);
        prs[1] = make_float4(ls[4], ls[5], ls[6], ls[7]);
        prq[0] = make_float4(lq[0], lq[1], lq[2], lq[3]);
        prq[1] = make_float4(lq[4], lq[5], lq[6], lq[7]);
    }
    __syncthreads();
    if (tid < DD) {
        float s = 0.f, q = 0.f;
        #pragma unroll
        for (int w = 0; w < 8; w++) { s += rs[w][tid]; q += rq[w][tid]; }
        atomicAdd(&g_sum[tid], s);
        atomicAdd(&g_sumsq[tid], q);
    }
}

// --------- fused BN params + normalize + dropout (bitmask instead of u) ----------
__global__ void __launch_bounds__(256) final_kernel(const float* __restrict__ gamma,
                                                    const float* __restrict__ beta,
                                                    float* __restrict__ z) {
    __shared__ float sc[DD], sh[DD];
    const int tid = threadIdx.x;
    if (tid < DD) {
        float mean = g_sum[tid] * (1.0f / NN);
        float var  = g_sumsq[tid] * (1.0f / NN) - mean * mean;
        float s    = gamma[tid] * rsqrtf(var + 1e-5f);
        sc[tid] = s;
        sh[tid] = beta[tid] - mean * s;
    }
    __syncthreads();

    int gid = blockIdx.x * blockDim.x + tid;
    if (gid >= NN * 32) return;
    int j4 = (gid & 31) * 4;

    float4 v = ((const float4*)z)[gid];
    unsigned int m = g_mask[gid >> 3] >> ((gid & 7) * 4);   // 4 keep-bits
    const float inv_keep = 1.0f / 0.9f;

    float4 r;
    r.x = (m & 1u) ? (v.x * sc[j4 + 0] + sh[j4 + 0]) * inv_keep : 0.0f;
    r.y = (m & 2u) ? (v.y * sc[j4 + 1] + sh[j4 + 1]) * inv_keep : 0.0f;
    r.z = (m & 4u) ? (v.z * sc[j4 + 2] + sh[j4 + 2]) * inv_keep : 0.0f;
    r.w = (m & 8u) ? (v.w * sc[j4 + 3] + sh[j4 + 3]) * inv_keep : 0.0f;
    ((float4*)z)[gid] = r;
}

// ----- launch: gemm∥mask side streams; deg -> scanf -> fill; gather; final -------
extern "C" void kernel_launch(void* const* d_in, const int* in_sizes, int n_in,
                              void* d_out, int out_size) {
    const float* x      = (const float*)d_in[0];
    const float* weight = (const float*)d_in[1];
    const float* bias   = (const float*)d_in[2];
    const float* gamma  = (const float*)d_in[3];
    const float* beta   = (const float*)d_in[4];
    const float* drop_u = (const float*)d_in[5];
    const unsigned int* eidx = (const unsigned int*)d_in[6];

    float* z = (float*)d_out;

    static cudaStream_t s2 = nullptr, s3 = nullptr;
    static cudaEvent_t evf = nullptr, evd = nullptr, evj = nullptr, evm = nullptr;
    if (s2 == nullptr) {
        cudaStreamCreateWithFlags(&s2, cudaStreamNonBlocking);
        cudaStreamCreateWithFlags(&s3, cudaStreamNonBlocking);
        cudaEventCreateWithFlags(&evf, cudaEventDisableTiming);
        cudaEventCreateWithFlags(&evd, cudaEventDisableTiming);
        cudaEventCreateWithFlags(&evj, cudaEventDisableTiming);
        cudaEventCreateWithFlags(&evm, cudaEventDisableTiming);
    }

    // fork: GEMM (s2) and dropout-mask (s3) depend only on inputs
    cudaEventRecord(evf, 0);
    cudaStreamWaitEvent(s2, evf, 0);
    cudaStreamWaitEvent(s3, evf, 0);
    gemm_kernel<<<(NN + 31) / 32, 128, 0, s2>>>(x, weight);
    mask_kernel<<<(NN * DD) / 256, 256, 0, s3>>>(drop_u);
    cudaEventRecord(evm, s3);

    // main chain: edge preprocessing
    deg_kernel<<<(NE + 255) / 256, 256>>>(eidx);
    scanf_kernel<<<SCAN_G, SCAN_B>>>();
    cudaEventRecord(evd, 0);                     // dinv ready
    fill_kernel<<<(NE + 255) / 256, 256>>>(eidx);

    // side stream: prescale needs GEMM + dinv
    cudaStreamWaitEvent(s2, evd, 0);
    prescale_kernel<<<(NN * 32 + 255) / 256, 256, 0, s2>>>();
    cudaEventRecord(evj, s2);

    // join: gather needs CSR + prescaled rows
    cudaStreamWaitEvent(0, evj, 0);
    gather_kernel<<<592, 256>>>(bias, z);

    // epilogue needs BN stats + mask
    cudaStreamWaitEvent(0, evm, 0);
    final_kernel<<<(NN * 32 + 255) / 256, 256>>>(gamma, beta, z);
}

// round 14
// speedup vs baseline: 1.6001x; 1.4473x over previous
#include <cuda_runtime.h>
#include <cuda_fp16.h>

#define NN 50000
#define NE 600000
#define DD 128
#define SCAN_B 1024
#define SCAN_G ((NN + SCAN_B - 1) / SCAN_B)   // 49
#define LDA 132                                // padded halves/row in smem (bank spread)
#define GEMM_SMEM (2 * 128 * LDA * 2)          // A tile + Wt tile, 67584 B

// ---------------- scratch (static device globals; no allocation) ----------------
__device__ __half g_xwh[NN * DD];               // fp16(x @ W), 12.8 MB (L2-resident)
__device__ int    g_degi[NN];                   // zero at load; fill re-zeroes
__device__ int    g_start[NN];
__device__ int    g_cur[NN];
__device__ unsigned int g_adj[NE];              // src per edge (CSR by dst)
__device__ float  g_dinv[NN];
__device__ int    g_bsum[SCAN_G];
__device__ unsigned int g_ready;                // scanf sync; fill resets to 0
__device__ float  g_sum[DD];                    // zeroed in scanf each run
__device__ float  g_sumsq[DD];

// ---- local int64/int32 detection: values < 50000 => int64 odd words all zero ----
__device__ __forceinline__ int detect_is64(const unsigned int* __restrict__ e) {
    int is64 = 1;
    #pragma unroll
    for (int i = 0; i < 16; i++)
        if (e[2 * i + 1] != 0u) { is64 = 0; break; }
    return is64;
}

// ---------------- degree over dst ----------------
__global__ void deg_kernel(const unsigned int* __restrict__ e) {
    __shared__ int s64;
    if (threadIdx.x == 0) s64 = detect_is64(e);
    __syncthreads();
    int t = blockIdx.x * blockDim.x + threadIdx.x;
    if (t >= NE) return;
    int d;
    if (s64) d = (int)((const long long*)e)[NE + t];
    else     d = ((const int*)e)[NE + t];
    atomicAdd(&g_degi[d], 1);
}

// ------- fused scan: dinv + block scan + cross-block sync + start/cur ------------
__global__ void __launch_bounds__(SCAN_B) scanf_kernel() {
    __shared__ int wsums[32];
    __shared__ int bpart[2];
    const int tid = threadIdx.x, lane = tid & 31, wid = tid >> 5;
    const int bid = blockIdx.x;

    if (bid == 0 && tid < DD) { g_sum[tid] = 0.0f; g_sumsq[tid] = 0.0f; }

    const int i = bid * SCAN_B + tid;
    int d = (i < NN) ? g_degi[i] : 0;
    if (i < NN) g_dinv[i] = rsqrtf((float)d + 1.0f);   // +1 = self loop

    int v = d;
    #pragma unroll
    for (int o = 1; o < 32; o <<= 1) {
        int t = __shfl_up_sync(0xffffffffu, v, o);
        if (lane >= o) v += t;
    }
    if (lane == 31) wsums[wid] = v;
    __syncthreads();
    if (wid == 0) {
        int wv = wsums[lane];
        #pragma unroll
        for (int o = 1; o < 32; o <<= 1) {
            int t = __shfl_up_sync(0xffffffffu, wv, o);
            if (lane >= o) wv += t;
        }
        wsums[lane] = wv;
    }
    __syncthreads();

    if (tid == 0) {
        g_bsum[bid] = wsums[31];
        __threadfence();
        atomicAdd(&g_ready, 1u);
        volatile unsigned int* r = &g_ready;
        while (*r < (unsigned)SCAN_G) __nanosleep(32);
        __threadfence();
    }
    __syncthreads();

    if (tid < 64) {
        int t = (tid < bid) ? g_bsum[tid] : 0;
        #pragma unroll
        for (int o = 16; o > 0; o >>= 1) t += __shfl_down_sync(0xffffffffu, t, o);
        if ((tid & 31) == 0) bpart[tid >> 5] = t;
    }
    __syncthreads();

    if (i < NN) {
        int excl = bpart[0] + bpart[1] + (wid > 0 ? wsums[wid - 1] : 0) + (v - d);
        g_start[i] = excl;
        g_cur[i]   = excl;
    }
}

// -------- adjacency fill; re-zero degi + reset scan sync for next replay ---------
__global__ void fill_kernel(const unsigned int* __restrict__ e) {
    __shared__ int s64;
    if (threadIdx.x == 0) s64 = detect_is64(e);
    __syncthreads();
    int t = blockIdx.x * blockDim.x + threadIdx.x;
    if (t >= NE) return;
    if (t < NN) g_degi[t] = 0;
    if (t == 0) g_ready = 0u;
    int s, d;
    if (s64) {
        s = (int)((const long long*)e)[t];
        d = (int)((const long long*)e)[NE + t];
    } else {
        s = ((const int*)e)[t];
        d = ((const int*)e)[NE + t];
    }
    int p = atomicAdd(&g_cur[d], 1);
    g_adj[p] = (unsigned int)s;
}

// ---- GEMM via tensor cores: g_xwh = fp16(x @ W), mma.sync m16n8k16 f16/f32 ------
// Block = 256 thr (8 warps) computes 128 rows x 128 cols. Warp = 16 rows x 128 cols.
__global__ void __launch_bounds__(256) gemm_tc_kernel(const float* __restrict__ x,
                                                      const float* __restrict__ W) {
    extern __shared__ __half smem[];
    __half* As = smem;                  // [128][LDA] x tile (row-major, fp16)
    __half* Bs = smem + 128 * LDA;      // [128][LDA] Wt: Bs[n][k] = W[k][n] (fp16)

    const int tid = threadIdx.x;
    const int r0  = blockIdx.x * 128;

    // load x tile -> fp16 smem (zero-fill past NN)
    for (int i = tid; i < 128 * 32; i += 256) {
        int row = i >> 5, c4 = i & 31;
        float4 v = make_float4(0.f, 0.f, 0.f, 0.f);
        if (r0 + row < NN) v = ((const float4*)x)[(size_t)(r0 + row) * 32 + c4];
        __half2 h01 = __floats2half2_rn(v.x, v.y);
        __half2 h23 = __floats2half2_rn(v.z, v.w);
        *(uint2*)(As + row * LDA + c4 * 4) =
            make_uint2(*(unsigned*)&h01, *(unsigned*)&h23);
    }
    // load W transposed: Bs[n][k] = W[k*128 + n]  (W is L2-hot: 64 KB)
    for (int i = tid; i < 128 * 128; i += 256) {
        int k = i >> 7, n = i & 127;
        Bs[n * LDA + k] = __float2half_rn(W[i]);
    }
    __syncthreads();

    const int warp = tid >> 5, lane = tid & 31;
    const int gid = lane >> 2, tig = lane & 3;
    const int wr = warp * 16;

    float c[16][4];
    #pragma unroll
    for (int t = 0; t < 16; t++) { c[t][0] = c[t][1] = c[t][2] = c[t][3] = 0.f; }

    #pragma unroll
    for (int ks = 0; ks < 8; ks++) {
        const int k0 = ks * 16;
        // A fragment (m16k16, row-major): {(g,k0+2t..+1),(g+8,..),(g,k0+2t+8..),(g+8,..+8)}
        unsigned a0 = *(unsigned*)(As + (wr + gid)     * LDA + k0 + 2 * tig);
        unsigned a1 = *(unsigned*)(As + (wr + gid + 8) * LDA + k0 + 2 * tig);
        unsigned a2 = *(unsigned*)(As + (wr + gid)     * LDA + k0 + 2 * tig + 8);
        unsigned a3 = *(unsigned*)(As + (wr + gid + 8) * LDA + k0 + 2 * tig + 8);
        #pragma unroll
        for (int t = 0; t < 16; t++) {
            // B fragment (k16n8, col layout): reg0 k=k0+2t.., reg1 k=k0+2t+8.., n=t*8+gid
            unsigned b0 = *(unsigned*)(Bs + (t * 8 + gid) * LDA + k0 + 2 * tig);
            unsigned b1 = *(unsigned*)(Bs + (t * 8 + gid) * LDA + k0 + 2 * tig + 8);
            asm volatile(
                "mma.sync.aligned.m16n8k16.row.col.f32.f16.f16.f32 "
                "{%0,%1,%2,%3}, {%4,%5,%6,%7}, {%8,%9}, {%0,%1,%2,%3};"
                : "+f"(c[t][0]), "+f"(c[t][1]), "+f"(c[t][2]), "+f"(c[t][3])
                : "r"(a0), "r"(a1), "r"(a2), "r"(a3), "r"(b0), "r"(b1));
        }
    }

    // store: c0,c1 -> (row gid, col 2tig..+1); c2,c3 -> (row gid+8, same cols)
    const int row0 = r0 + wr + gid;
    const int row1 = row0 + 8;
    #pragma unroll
    for (int t = 0; t < 16; t++) {
        const int col = t * 8 + 2 * tig;
        if (row0 < NN) {
            __half2 h = __floats2half2_rn(c[t][0], c[t][1]);
            *(unsigned*)(g_xwh + (size_t)row0 * DD + col) = *(unsigned*)&h;
        }
        if (row1 < NN) {
            __half2 h = __floats2half2_rn(c[t][2], c[t][3]);
            *(unsigned*)(g_xwh + (size_t)row1 * DD + col) = *(unsigned*)&h;
        }
    }
}

// ---- gather: warp/node, 2 edges in flight, fp16 rows, per-edge dinv[s] ----------
__device__ __forceinline__ float2 h2f(unsigned int h) {
    __half2 hh = *(__half2*)&h;
    return __half22float2(hh);
}

__global__ void __launch_bounds__(256) gather_kernel(const float* __restrict__ bias,
                                                     float* __restrict__ z) {
    const int tid   = threadIdx.x;
    const int lane  = tid & 31;
    const int wid   = tid >> 5;
    const int g     = lane >> 4;   // half-warp id (0/1): edge parity
    const int hl    = lane & 15;   // lane in half-warp -> cols 8*hl..8*hl+7
    const int warpg = (blockIdx.x * 256 + tid) >> 5;
    const int nwarp = gridDim.x * 8;

    const uint4*  __restrict__ xws   = (const uint4*)g_xwh;   // row = 16 uint4
    const float4* __restrict__ bias4 = (const float4*)bias;
    float4*       __restrict__ z4    = (float4*)z;

    const float4 b0 = bias4[2 * hl];
    const float4 b1 = bias4[2 * hl + 1];
    float ls[8], lq[8];
    #pragma unroll
    for (int k = 0; k < 8; k++) { ls[k] = 0.f; lq[k] = 0.f; }

    for (int node = warpg; node < NN; node += nwarp) {
        const int beg = g_start[node];
        const int end = g_cur[node];
        const float di = g_dinv[node];

        float a[8];
        #pragma unroll
        for (int k = 0; k < 8; k++) a[k] = 0.f;

        // self loop: xwh[node]*di here, outer *di below makes it di^2 (half-warp 0)
        if (g == 0) {
            uint4 r = __ldcg(&xws[(size_t)node * 16 + hl]);
            float2 p0 = h2f(r.x), p1 = h2f(r.y), p2 = h2f(r.z), p3 = h2f(r.w);
            a[0] = p0.x * di; a[1] = p0.y * di; a[2] = p1.x * di; a[3] = p1.y * di;
            a[4] = p2.x * di; a[5] = p2.y * di; a[6] = p3.x * di; a[7] = p3.y * di;
        }

        for (int base = beg; base < end; base += 32) {
            const int cnt = min(32, end - base);
            unsigned int sv = (lane < cnt) ? g_adj[base + lane] : 0u;  // coalesced
            float dv = __ldg(&g_dinv[sv]);                              // L1-hot table
            #pragma unroll 4
            for (int j = 0; j < cnt; j += 2) {
                int ei = j + g;
                unsigned int sj = __shfl_sync(0xffffffffu, sv, ei & 31);
                float        nj = __shfl_sync(0xffffffffu, dv, ei & 31);
                if (ei < cnt) {
                    uint4 r = __ldcg(&xws[(size_t)sj * 16 + hl]);
                    float2 p0 = h2f(r.x), p1 = h2f(r.y), p2 = h2f(r.z), p3 = h2f(r.w);
                    a[0] += p0.x * nj; a[1] += p0.y * nj;
                    a[2] += p1.x * nj; a[3] += p1.y * nj;
                    a[4] += p2.x * nj; a[5] += p2.y * nj;
                    a[6] += p3.x * nj; a[7] += p3.y * nj;
                }
            }
        }

        // combine the two half-warps
        #pragma unroll
        for (int k = 0; k < 8; k++) a[k] += __shfl_xor_sync(0xffffffffu, a[k], 16);

        if (g == 0) {
            float4 v0, v1;
            v0.x = fmaxf(a[0] * di + b0.x, 0.0f);
            v0.y = fmaxf(a[1] * di + b0.y, 0.0f);
            v0.z = fmaxf(a[2] * di + b0.z, 0.0f);
            v0.w = fmaxf(a[3] * di + b0.w, 0.0f);
            v1.x = fmaxf(a[4] * di + b1.x, 0.0f);
            v1.y = fmaxf(a[5] * di + b1.y, 0.0f);
            v1.z = fmaxf(a[6] * di + b1.z, 0.0f);
            v1.w = fmaxf(a[7] * di + b1.w, 0.0f);
            z4[(size_t)node * 32 + 2 * hl]     = v0;
            z4[(size_t)node * 32 + 2 * hl + 1] = v1;
            ls[0] += v0.x; ls[1] += v0.y; ls[2] += v0.z; ls[3] += v0.w;
            ls[4] += v1.x; ls[5] += v1.y; ls[6] += v1.z; ls[7] += v1.w;
            lq[0] += v0.x * v0.x; lq[1] += v0.y * v0.y; lq[2] += v0.z * v0.z; lq[3] += v0.w * v0.w;
            lq[4] += v1.x * v1.x; lq[5] += v1.y * v1.y; lq[6] += v1.z * v1.z; lq[7] += v1.w * v1.w;
        }
    }

    __shared__ float rs[8][DD];
    __shared__ float rq[8][DD];
    if (g == 0) {
        float4* prs = (float4*)&rs[wid][hl * 8];
        float4* prq = (float4*)&rq[wid][hl * 8];
        prs[0] = make_float4(ls[0], ls[1], ls[2], ls[3]);
        prs[1] = make_float4(ls[4], ls[5], ls[6], ls[7]);
        prq[0] = make_float4(lq[0], lq[1], lq[2], lq[3]);
        prq[1] = make_float4(lq[4], lq[5], lq[6], lq[7]);
    }
    __syncthreads();
    if (tid < DD) {
        float s = 0.f, q = 0.f;
        #pragma unroll
        for (int w = 0; w < 8; w++) { s += rs[w][tid]; q += rq[w][tid]; }
        atomicAdd(&g_sum[tid], s);
        atomicAdd(&g_sumsq[tid], q);
    }
}

// --------- fused BN params + normalize + dropout (R9 form: reads u) --------------
__global__ void __launch_bounds__(256) final_kernel(const float* __restrict__ gamma,
                                                    const float* __restrict__ beta,
                                                    const float* __restrict__ u,
                                                    float* __restrict__ z) {
    __shared__ float sc[DD], sh[DD];
    const int tid = threadIdx.x;
    if (tid < DD) {
        float mean = g_sum[tid] * (1.0f / NN);
        float var  = g_sumsq[tid] * (1.0f / NN) - mean * mean;
        float s    = gamma[tid] * rsqrtf(var + 1e-5f);
        sc[tid] = s;
        sh[tid] = beta[tid] - mean * s;
    }
    __syncthreads();

    int gid = blockIdx.x * blockDim.x + tid;
    if (gid >= NN * 32) return;
    int j4 = (gid & 31) * 4;

    float4 v  = ((const float4*)z)[gid];
    float4 uu = ((const float4*)u)[gid];
    const float inv_keep = 1.0f / 0.9f;

    float4 r;
    r.x = (uu.x > 0.1f) ? (v.x * sc[j4 + 0] + sh[j4 + 0]) * inv_keep : 0.0f;
    r.y = (uu.y > 0.1f) ? (v.y * sc[j4 + 1] + sh[j4 + 1]) * inv_keep : 0.0f;
    r.z = (uu.z > 0.1f) ? (v.z * sc[j4 + 2] + sh[j4 + 2]) * inv_keep : 0.0f;
    r.w = (uu.w > 0.1f) ? (v.w * sc[j4 + 3] + sh[j4 + 3]) * inv_keep : 0.0f;
    ((float4*)z)[gid] = r;
}

// --------- launch: gemm_tc (s2) ∥ deg -> scanf -> fill; join; gather; final ------
extern "C" void kernel_launch(void* const* d_in, const int* in_sizes, int n_in,
                              void* d_out, int out_size) {
    const float* x      = (const float*)d_in[0];
    const float* weight = (const float*)d_in[1];
    const float* bias   = (const float*)d_in[2];
    const float* gamma  = (const float*)d_in[3];
    const float* beta   = (const float*)d_in[4];
    const float* drop_u = (const float*)d_in[5];
    const unsigned int* eidx = (const unsigned int*)d_in[6];

    float* z = (float*)d_out;

    static cudaStream_t s2 = nullptr;
    static cudaEvent_t evf = nullptr, evj = nullptr;
    if (s2 == nullptr) {
        cudaStreamCreateWithFlags(&s2, cudaStreamNonBlocking);
        cudaEventCreateWithFlags(&evf, cudaEventDisableTiming);
        cudaEventCreateWithFlags(&evj, cudaEventDisableTiming);
        cudaFuncSetAttribute(gemm_tc_kernel,
                             cudaFuncAttributeMaxDynamicSharedMemorySize, GEMM_SMEM);
    }

    // fork: tensor-core GEMM depends only on inputs; hidden under the preproc chain
    cudaEventRecord(evf, 0);
    cudaStreamWaitEvent(s2, evf, 0);
    gemm_tc_kernel<<<(NN + 127) / 128, 256, GEMM_SMEM, s2>>>(x, weight);
    cudaEventRecord(evj, s2);

    // main chain: edge preprocessing
    deg_kernel<<<(NE + 255) / 256, 256>>>(eidx);
    scanf_kernel<<<SCAN_G, SCAN_B>>>();
    fill_kernel<<<(NE + 255) / 256, 256>>>(eidx);

    // join: gather needs CSR + fp16 rows
    cudaStreamWaitEvent(0, evj, 0);
    gather_kernel<<<592, 256>>>(bias, z);

    // epilogue
    final_kernel<<<(NN * 32 + 255) / 256, 256>>>(gamma, beta, drop_u, z);
}